// round 15
// baseline (speedup 1.0000x reference)
#include <cuda_runtime.h>
#include <cuda_bf16.h>
#include <cuda_fp16.h>
#include <stdint.h>
#include <math.h>

// Problem constants
#define Nn    50000
#define Mpad  50048
#define Ee    800000
#define FEAT  512
#define HEADS 8
#define HID   64
#define C1    512
#define NC    64
#define ALPHA 0.2f

// ---------------- scratch -----------------------------------------------------
__device__ float g_fd1[Nn * HEADS];
__device__ float g_fs1[Nn * HEADS];
__device__ float g_fd2[Nn];
__device__ float g_fs2[Nn];
__device__ int   g_cnt[Nn];   // always zero at kernel_launch entry (scan re-zeros)
__device__ int   g_off[Nn + 1];
__device__ int   g_cur[Nn];
__device__ int   g_cols[Ee];

// fp16 operands / intermediates
__device__ __align__(256) __half g_xh [(size_t)Mpad * 512];   // x in fp16
__device__ __align__(256) __half g_bh [512 * 512];            // W1t in fp16
__device__ __align__(256) __half g_Whb[(size_t)Nn * 512];     // layer1 Wh in fp16
__device__ __align__(256) __half g_h1 [(size_t)Mpad * 512];   // h1 fp16 (pad rows stay 0)
__device__ __align__(256) __half g_b2 [64 * 512];             // W_out_t in fp16
__device__ __align__(256) __half g_Wh2h[(size_t)Nn * 64];     // layer2 Wh in fp16

// ---------------- PTX helpers --------------------------------------------------
__device__ __forceinline__ uint32_t smem_u32(const void* p) {
    uint32_t a;
    asm("{ .reg .u64 t; cvta.to.shared.u64 t, %1; cvt.u32.u64 %0, t; }" : "=r"(a) : "l"(p));
    return a;
}
__device__ __forceinline__ void cpa16(uint32_t dst, const void* src) {
    asm volatile("cp.async.cg.shared.global [%0], [%1], 16;" :: "r"(dst), "l"(src));
}
__device__ __forceinline__ void cpa_commit() {
    asm volatile("cp.async.commit_group;" ::: "memory");
}
template <int N> __device__ __forceinline__ void cpa_wait() {
    asm volatile("cp.async.wait_group %0;" :: "n"(N) : "memory");
}
__device__ __forceinline__ void ldm4(uint32_t* r, uint32_t addr) {
    asm volatile("ldmatrix.sync.aligned.m8n8.x4.shared.b16 {%0,%1,%2,%3}, [%4];"
                 : "=r"(r[0]), "=r"(r[1]), "=r"(r[2]), "=r"(r[3]) : "r"(addr));
}
__device__ __forceinline__ void mma16816h(float* c, const uint32_t* a,
                                          uint32_t b0, uint32_t b1) {
    asm volatile(
        "mma.sync.aligned.m16n8k16.row.col.f32.f16.f16.f32 "
        "{%0,%1,%2,%3}, {%4,%5,%6,%7}, {%8,%9}, {%0,%1,%2,%3};"
        : "+f"(c[0]), "+f"(c[1]), "+f"(c[2]), "+f"(c[3])
        : "r"(a[0]), "r"(a[1]), "r"(a[2]), "r"(a[3]), "r"(b0), "r"(b1));
}

// ---------------- conversion / init kernels (hist fused into cvt_x) -------------
__global__ void k_cvt_x_hist(const float* __restrict__ x, const int* __restrict__ row) {
    long long i4 = (long long)blockIdx.x * blockDim.x + threadIdx.x;
    if (i4 < Ee) atomicAdd(&g_cnt[row[i4]], 1);
    if (i4 >= (long long)Mpad * 128) return;
    long long r = i4 >> 7;
    float4 v = make_float4(0.f, 0.f, 0.f, 0.f);
    if (r < Nn) v = ((const float4*)x)[i4];
    __half2 p0, p1;
    p0.x = __float2half_rn(v.x); p0.y = __float2half_rn(v.y);
    p1.x = __float2half_rn(v.z); p1.y = __float2half_rn(v.w);
    *(__half2*)(g_xh + i4 * 4)     = p0;
    *(__half2*)(g_xh + i4 * 4 + 2) = p1;
}

__global__ void k_init_misc(const float* __restrict__ W,
                            const float* __restrict__ W_out) {
    int idx = blockIdx.x * blockDim.x + threadIdx.x;
    if (idx < 512 * 512) {
        int n = idx >> 9, k = idx & 511;
        float v = W[(size_t)(n >> 6) * (512 * 64) + (size_t)k * 64 + (n & 63)];
        g_bh[idx] = __float2half_rn(v);
    }
    if (idx < 64 * 512) {
        int n = idx >> 9, k = idx & 511;
        g_b2[idx] = __float2half_rn(W_out[(size_t)k * 64 + n]);
    }
}

// ---------------- fp16 HMMA GEMM1 (+f1 epilogue), 2 CTAs/SM, 1 sync/iter --------
#define A_OFF 0
#define B_OFF 10240
#define STAGE 20480
#define SMEM_GEMM_TOTAL (2 * STAGE)

__device__ __forceinline__ void load_stage(uint32_t s, int t, int m0, int n0, int kc) {
    int k0 = kc * 32;
#pragma unroll
    for (int i = 0; i < 2; i++) {
        int idx = t + i * 256;
        int r = idx >> 2;
        int c = idx & 3;
        uint32_t d = s + (uint32_t)(r * 80 + c * 16);
        size_t sa = (size_t)(m0 + r) * 512 + k0 + c * 8;
        size_t sbg = (size_t)(n0 + r) * 512 + k0 + c * 8;
        cpa16(d + A_OFF, g_xh + sa);
        cpa16(d + B_OFF, g_bh + sbg);
    }
    cpa_commit();
}

__global__ void __launch_bounds__(256, 2) k_gemm1_mma(const float* __restrict__ a_vec) {
    extern __shared__ char smem[];
    __shared__ float s_ad[2][64], s_as[2][64];
    uint32_t sb = smem_u32(smem);
    const int t = threadIdx.x;
    const int lane = t & 31, w = t >> 5;
    const int wm = w & 3, wn = w >> 2;
    const int m0 = blockIdx.x * 128, n0 = blockIdx.y * 128;

    if (t < 128) {
        int hh = t >> 6, j = t & 63;
        int gh = blockIdx.y * 2 + hh;
        s_ad[hh][j] = a_vec[gh * 128 + j];
        s_as[hh][j] = a_vec[gh * 128 + 64 + j];
    }

    float acc[2][8][4];
#pragma unroll
    for (int mf = 0; mf < 2; mf++)
#pragma unroll
        for (int nf = 0; nf < 8; nf++)
#pragma unroll
            for (int q = 0; q < 4; q++) acc[mf][nf][q] = 0.f;

    load_stage(sb, t, m0, n0, 0);

    const int a_row = wm * 32 + (lane & 15);
    const int a_colb = (lane >> 4) * 8;
    const int b_row = wn * 64 + ((lane >> 4) & 1) * 8 + (lane & 7);
    const int b_colb = ((lane >> 3) & 1) * 8;

    for (int kc = 0; kc < 16; kc++) {
        uint32_t s = sb + (uint32_t)(kc & 1) * STAGE;
        cpa_wait<0>();
        __syncthreads();   // stage kc ready; all warps finished reading buf (kc+1)&1
        if (kc + 1 < 16) load_stage(sb + (uint32_t)((kc + 1) & 1) * STAGE, t, m0, n0, kc + 1);

#pragma unroll
        for (int ks = 0; ks < 2; ks++) {
            uint32_t ah[2][4];
#pragma unroll
            for (int mf = 0; mf < 2; mf++) {
                uint32_t ad = s + A_OFF +
                    (uint32_t)((a_row + mf * 16) * 80 + (ks * 16 + a_colb) * 2);
                ldm4(ah[mf], ad);
            }
#pragma unroll
            for (int nb = 0; nb < 4; nb++) {
                uint32_t bh4[4];
                uint32_t bd = s + B_OFF +
                    (uint32_t)((b_row + nb * 16) * 80 + (ks * 16 + b_colb) * 2);
                ldm4(bh4, bd);
#pragma unroll
                for (int mf = 0; mf < 2; mf++)
#pragma unroll
                    for (int half = 0; half < 2; half++) {
                        float* c = acc[mf][nb * 2 + half];
                        mma16816h(c, ah[mf], bh4[half * 2], bh4[half * 2 + 1]);
                    }
            }
        }
    }

    const int ghead = blockIdx.y * 2 + wn;
#pragma unroll
    for (int mf = 0; mf < 2; mf++) {
        int rbase = m0 + wm * 32 + mf * 16 + (lane >> 2);
#pragma unroll
        for (int nf = 0; nf < 8; nf++) {
            int cc = n0 + wn * 64 + nf * 8 + (lane & 3) * 2;
            float* c = acc[mf][nf];
            if (rbase < Nn) {
                __half2 p;
                p.x = __float2half_rn(c[0]);
                p.y = __float2half_rn(c[1]);
                *(__half2*)(g_Whb + (size_t)rbase * 512 + cc) = p;
            }
            if (rbase + 8 < Nn) {
                __half2 p;
                p.x = __float2half_rn(c[2]);
                p.y = __float2half_rn(c[3]);
                *(__half2*)(g_Whb + (size_t)(rbase + 8) * 512 + cc) = p;
            }
        }
#pragma unroll
        for (int half = 0; half < 2; half++) {
            float pd = 0.f, ps = 0.f;
#pragma unroll
            for (int nf = 0; nf < 8; nf++) {
                int j0 = nf * 8 + (lane & 3) * 2;
                float c0 = acc[mf][nf][half * 2 + 0];
                float c1 = acc[mf][nf][half * 2 + 1];
                pd += c0 * s_ad[wn][j0] + c1 * s_ad[wn][j0 + 1];
                ps += c0 * s_as[wn][j0] + c1 * s_as[wn][j0 + 1];
            }
            pd += __shfl_xor_sync(0xffffffffu, pd, 1);
            pd += __shfl_xor_sync(0xffffffffu, pd, 2);
            ps += __shfl_xor_sync(0xffffffffu, ps, 1);
            ps += __shfl_xor_sync(0xffffffffu, ps, 2);
            int r = rbase + half * 8;
            if ((lane & 3) == 0 && r < Nn) {
                g_fd1[r * 8 + ghead] = pd;
                g_fs1[r * 8 + ghead] = ps;
            }
        }
    }
}

// ---------------- fp16 HMMA GEMM2 (+f2 epilogue), 2 CTAs/SM, 1 sync/iter --------
#define A2_OFF 0
#define B2_OFF 10240
#define STAGE2 15360
#define SMEM_GEMM2_TOTAL (2 * STAGE2)

__device__ __forceinline__ void load_stage2(uint32_t s, int t, int m0, int kc) {
    int k0 = kc * 32;
#pragma unroll
    for (int i = 0; i < 2; i++) {
        int idx = t + i * 256;
        int r = idx >> 2;
        int c = idx & 3;
        uint32_t d = s + (uint32_t)(r * 80 + c * 16);
        size_t sa = (size_t)(m0 + r) * 512 + k0 + c * 8;
        cpa16(d + A2_OFF, g_h1 + sa);
    }
    if (t < 256) {
        int r = t >> 2, c = t & 3;
        uint32_t d = s + (uint32_t)(r * 80 + c * 16);
        size_t sbg = (size_t)r * 512 + k0 + c * 8;
        cpa16(d + B2_OFF, g_b2 + sbg);
    }
    cpa_commit();
}

__global__ void __launch_bounds__(256, 2) k_gemm2_mma(const float* __restrict__ a_out) {
    extern __shared__ char smem[];
    __shared__ float s_a2d[64], s_a2s[64];
    __shared__ float s_pd[2][128], s_ps[2][128];
    uint32_t sb = smem_u32(smem);
    const int t = threadIdx.x;
    const int lane = t & 31, w = t >> 5;
    const int wm = w & 3, wn = w >> 2;
    const int m0 = blockIdx.x * 128;

    if (t < 64) {
        s_a2d[t] = a_out[t];
        s_a2s[t] = a_out[64 + t];
    }

    float acc[2][4][4];
#pragma unroll
    for (int mf = 0; mf < 2; mf++)
#pragma unroll
        for (int nf = 0; nf < 4; nf++)
#pragma unroll
            for (int q = 0; q < 4; q++) acc[mf][nf][q] = 0.f;

    load_stage2(sb, t, m0, 0);

    const int a_row = wm * 32 + (lane & 15);
    const int a_colb = (lane >> 4) * 8;
    const int b_row = wn * 32 + ((lane >> 4) & 1) * 8 + (lane & 7);
    const int b_colb = ((lane >> 3) & 1) * 8;

    for (int kc = 0; kc < 16; kc++) {
        uint32_t s = sb + (uint32_t)(kc & 1) * STAGE2;
        cpa_wait<0>();
        __syncthreads();
        if (kc + 1 < 16) load_stage2(sb + (uint32_t)((kc + 1) & 1) * STAGE2, t, m0, kc + 1);

#pragma unroll
        for (int ks = 0; ks < 2; ks++) {
            uint32_t ah[2][4];
#pragma unroll
            for (int mf = 0; mf < 2; mf++) {
                uint32_t ad = s + A2_OFF +
                    (uint32_t)((a_row + mf * 16) * 80 + (ks * 16 + a_colb) * 2);
                ldm4(ah[mf], ad);
            }
#pragma unroll
            for (int nb = 0; nb < 2; nb++) {
                uint32_t bh4[4];
                uint32_t bd = s + B2_OFF +
                    (uint32_t)((b_row + nb * 16) * 80 + (ks * 16 + b_colb) * 2);
                ldm4(bh4, bd);
#pragma unroll
                for (int mf = 0; mf < 2; mf++)
#pragma unroll
                    for (int half = 0; half < 2; half++) {
                        float* c = acc[mf][nb * 2 + half];
                        mma16816h(c, ah[mf], bh4[half * 2], bh4[half * 2 + 1]);
                    }
            }
        }
    }

#pragma unroll
    for (int mf = 0; mf < 2; mf++) {
        int rbase = m0 + wm * 32 + mf * 16 + (lane >> 2);
#pragma unroll
        for (int nf = 0; nf < 4; nf++) {
            int cc = wn * 32 + nf * 8 + (lane & 3) * 2;
            float* c = acc[mf][nf];
            if (rbase < Nn) {
                __half2 p;
                p.x = __float2half_rn(c[0]);
                p.y = __float2half_rn(c[1]);
                *(__half2*)(g_Wh2h + (size_t)rbase * 64 + cc) = p;
            }
            if (rbase + 8 < Nn) {
                __half2 p;
                p.x = __float2half_rn(c[2]);
                p.y = __float2half_rn(c[3]);
                *(__half2*)(g_Wh2h + (size_t)(rbase + 8) * 64 + cc) = p;
            }
        }
#pragma unroll
        for (int half = 0; half < 2; half++) {
            float pd = 0.f, ps = 0.f;
#pragma unroll
            for (int nf = 0; nf < 4; nf++) {
                int j0 = wn * 32 + nf * 8 + (lane & 3) * 2;
                float c0 = acc[mf][nf][half * 2 + 0];
                float c1 = acc[mf][nf][half * 2 + 1];
                pd += c0 * s_a2d[j0] + c1 * s_a2d[j0 + 1];
                ps += c0 * s_a2s[j0] + c1 * s_a2s[j0 + 1];
            }
            pd += __shfl_xor_sync(0xffffffffu, pd, 1);
            pd += __shfl_xor_sync(0xffffffffu, pd, 2);
            ps += __shfl_xor_sync(0xffffffffu, ps, 1);
            ps += __shfl_xor_sync(0xffffffffu, ps, 2);
            int rl = wm * 32 + mf * 16 + (lane >> 2) + half * 8;
            if ((lane & 3) == 0) {
                s_pd[wn][rl] = pd;
                s_ps[wn][rl] = ps;
            }
        }
    }
    __syncthreads();
    if (t < 128) {
        int r = m0 + t;
        if (r < Nn) {
            g_fd2[r] = s_pd[0][t] + s_pd[1][t];
            g_fs2[r] = s_ps[0][t] + s_ps[1][t];
        }
    }
}

// ---------------- CSR build ------------------------------------------------
__global__ void k_scan() {   // 1024 threads; re-zeros g_cnt after reading
    __shared__ int s_w[32];
    __shared__ int s_base, s_next;
    int t = threadIdx.x, lane = t & 31, wid = t >> 5;
    if (t == 0) s_base = 0;
    __syncthreads();
    for (int start = 0; start < Nn; start += 1024) {
        int i = start + t;
        int v = 0;
        if (i < Nn) { v = g_cnt[i]; g_cnt[i] = 0; }
        int sc = v;
#pragma unroll
        for (int d = 1; d < 32; d <<= 1) {
            int u = __shfl_up_sync(0xffffffffu, sc, d);
            if (lane >= d) sc += u;
        }
        if (lane == 31) s_w[wid] = sc;
        __syncthreads();
        if (wid == 0) {
            int wsc = s_w[lane];
#pragma unroll
            for (int d = 1; d < 32; d <<= 1) {
                int u = __shfl_up_sync(0xffffffffu, wsc, d);
                if (lane >= d) wsc += u;
            }
            s_w[lane] = wsc;
            if (lane == 31) s_next = wsc;
        }
        __syncthreads();
        int base = s_base;
        int warpoff = (wid == 0) ? 0 : s_w[wid - 1];
        int ex = base + warpoff + sc - v;
        if (i < Nn) { g_off[i] = ex; g_cur[i] = ex; }
        __syncthreads();
        if (t == 0) s_base = base + s_next;
        __syncthreads();
    }
    if (t == 0) g_off[Nn] = s_base;
}

__global__ void k_scatter(const int* __restrict__ row, const int* __restrict__ col) {
    int e = blockIdx.x * blockDim.x + threadIdx.x;
    if (e < Ee) {
        int p = atomicAdd(&g_cur[row[e]], 1);
        g_cols[p] = col[e];
    }
}

// ---------------- layer1: fused logits + online softmax + fp16 gather agg ----
__global__ void __launch_bounds__(256) k_agg1() {
    int i = blockIdx.x;
    int t = threadIdx.x;
    int o = g_off[i], oe = g_off[i + 1];
    __shared__ float s_rm[32][8], s_rs[32][8];
    __shared__ float s_mx[8], s_iv[8];
    __shared__ float s_att[32][8];
    __shared__ int   s_col[32];
    __shared__ float s_fd[8];
    int j = t >> 3, h = t & 7;

    if (t < 8) s_fd[t] = g_fd1[i * 8 + t];
    __syncthreads();
    float fdh = s_fd[h];

    // single online pass: max + sumexp
    float m = -3.4e38f, sa = 0.f;
    for (int p = o + j; p < oe; p += 32) {
        int c = g_cols[p];
        float v = fdh + g_fs1[c * 8 + h];
        v = v > 0.f ? v : ALPHA * v;
        float nm = fmaxf(m, v);
        sa = sa * __expf(m - nm) + __expf(v - nm);
        m = nm;
    }
    s_rm[j][h] = m;
    s_rs[j][h] = sa;
    __syncthreads();
#pragma unroll
    for (int s = 16; s > 0; s >>= 1) {
        if (j < s) {
            float m1 = s_rm[j][h], s1 = s_rs[j][h];
            float m2 = s_rm[j + s][h], s2 = s_rs[j + s][h];
            float M = fmaxf(m1, m2);
            s_rs[j][h] = s1 * __expf(m1 - M) + s2 * __expf(m2 - M);
            s_rm[j][h] = M;
        }
        __syncthreads();
    }
    if (j == 0) {
        s_mx[h] = (oe > o) ? s_rm[0][h] : 0.f;
        s_iv[h] = (oe > o) ? 1.f / fmaxf(s_rs[0][h], 1e-16f) : 0.f;
    }
    __syncthreads();

    // aggregation; dims (2t, 2t+1); head = t>>5
    int ha = t >> 5;
    float acc0 = 0.f, acc1 = 0.f;
    for (int base = o; base < oe; base += 32) {
        int cnt = min(32, oe - base);
        __syncthreads();
        if (j < cnt) {
            int c = g_cols[base + j];
            float v = fdh + g_fs1[c * 8 + h];
            v = v > 0.f ? v : ALPHA * v;
            s_att[j][h] = __expf(v - s_mx[h]) * s_iv[h];
        }
        if (t < cnt) s_col[t] = g_cols[base + t];
        __syncthreads();
        for (int q = 0; q < cnt; q++) {
            int c = s_col[q];
            const __half2* whc = (const __half2*)(g_Whb + (size_t)c * 512);
            float2 v = __half22float2(whc[t]);
            float wv = s_att[q][ha];
            acc0 = fmaf(wv, v.x, acc0);
            acc1 = fmaf(wv, v.y, acc1);
        }
    }
    float v0 = acc0 > 0.f ? acc0 : (__expf(acc0) - 1.f);
    float v1 = acc1 > 0.f ? acc1 : (__expf(acc1) - 1.f);
    __half2 p;
    p.x = __float2half_rn(v0);
    p.y = __float2half_rn(v1);
    *(__half2*)(g_h1 + (size_t)i * 512 + 2 * t) = p;
}

// ---------------- layer2: fused logits + online softmax + aggregation --------
__global__ void __launch_bounds__(64) k_agg2(float* __restrict__ out) {
    int i = blockIdx.x;
    int t = threadIdx.x;  // 64
    int o = g_off[i], oe = g_off[i + 1];
    __shared__ float s_rm[64], s_rs[64];
    __shared__ float s_att[64];
    __shared__ int   s_col[64];
    float fd = g_fd2[i];

    float m = -3.4e38f, sa = 0.f;
    for (int p = o + t; p < oe; p += 64) {
        float v = fd + g_fs2[g_cols[p]];
        v = v > 0.f ? v : ALPHA * v;
        float nm = fmaxf(m, v);
        sa = sa * __expf(m - nm) + __expf(v - nm);
        m = nm;
    }
    s_rm[t] = m;
    s_rs[t] = sa;
    __syncthreads();
#pragma unroll
    for (int s = 32; s > 0; s >>= 1) {
        if (t < s) {
            float m1 = s_rm[t], s1 = s_rs[t];
            float m2 = s_rm[t + s], s2 = s_rs[t + s];
            float M = fmaxf(m1, m2);
            s_rs[t] = s1 * __expf(m1 - M) + s2 * __expf(m2 - M);
            s_rm[t] = M;
        }
        __syncthreads();
    }
    float M = s_rm[0];
    float iv = (oe > o) ? 1.f / fmaxf(s_rs[0], 1e-16f) : 0.f;
    __syncthreads();

    float acc = 0.f;
    for (int base = o; base < oe; base += 64) {
        int cnt = min(64, oe - base);
        __syncthreads();
        if (t < cnt) {
            int c = g_cols[base + t];
            float v = fd + g_fs2[c];
            v = v > 0.f ? v : ALPHA * v;
            s_att[t] = __expf(v - M) * iv;
            s_col[t] = c;
        }
        __syncthreads();
        for (int q = 0; q < cnt; q++)
            acc = fmaf(s_att[q], __half2float(g_Wh2h[(size_t)s_col[q] * 64 + t]), acc);
    }
    out[(size_t)i * 64 + t] = acc;
}

// ---------------- launch -----------------------------------------------------
extern "C" void kernel_launch(void* const* d_in, const int* in_sizes, int n_in,
                              void* d_out, int out_size) {
    const float* x     = (const float*)d_in[0];
    const int*   row   = (const int*)  d_in[1];
    const int*   col   = (const int*)  d_in[2];
    const float* W     = (const float*)d_in[3];
    const float* a     = (const float*)d_in[4];
    const float* W_out = (const float*)d_in[5];
    const float* a_out = (const float*)d_in[6];
    float* out = (float*)d_out;

    const int EB = (Ee + 255) / 256;

    cudaFuncSetAttribute(k_gemm1_mma, cudaFuncAttributeMaxDynamicSharedMemorySize,
                         SMEM_GEMM_TOTAL);
    cudaFuncSetAttribute(k_gemm2_mma, cudaFuncAttributeMaxDynamicSharedMemorySize,
                         SMEM_GEMM2_TOTAL);

    k_cvt_x_hist<<<(int)(((long long)Mpad * 128 + 255) / 256), 256>>>(x, row); // 0
    k_init_misc<<<(512 * 512 + 255) / 256, 256>>>(W, W_out);                   // 1
    k_scan<<<1, 1024>>>();                                                     // 2
    k_gemm1_mma<<<dim3(Mpad / 128, 4), 256, SMEM_GEMM_TOTAL>>>(a);             // 3 <- profiled
    k_scatter<<<EB, 256>>>(row, col);                                          // 4
    k_agg1<<<Nn, 256>>>();                                                     // 5
    k_gemm2_mma<<<Mpad / 128, 256, SMEM_GEMM2_TOTAL>>>(a_out);                 // 6
    k_agg2<<<Nn, 64>>>(out);                                                   // 7
}

// round 16
// speedup vs baseline: 1.0501x; 1.0501x over previous
#include <cuda_runtime.h>
#include <cuda_bf16.h>
#include <cuda_fp16.h>
#include <stdint.h>
#include <math.h>

// Problem constants
#define Nn    50000
#define Mpad  50048
#define Ee    800000
#define FEAT  512
#define HEADS 8
#define HID   64
#define C1    512
#define NC    64
#define ALPHA 0.2f

// ---------------- scratch -----------------------------------------------------
__device__ float g_fd1[Nn * HEADS];
__device__ float g_fs1[Nn * HEADS];
__device__ float g_fd2[Nn];
__device__ float g_fs2[Nn];
__device__ int   g_cnt[Nn];
__device__ int   g_off[Nn + 1];
__device__ int   g_cur[Nn];
__device__ int   g_cols[Ee];

// fp16 operands / intermediates
__device__ __align__(256) __half g_xh [(size_t)Mpad * 512];   // x in fp16
__device__ __align__(256) __half g_bh [512 * 512];            // W1t in fp16
__device__ __align__(256) __half g_Whb[(size_t)Nn * 512];     // layer1 Wh in fp16
__device__ __align__(256) __half g_h1 [(size_t)Mpad * 512];   // h1 fp16 (pad rows stay 0)
__device__ __align__(256) __half g_b2 [64 * 512];             // W_out_t in fp16
__device__ __align__(256) __half g_Wh2h[(size_t)Nn * 64];     // layer2 Wh in fp16

// ---------------- PTX helpers --------------------------------------------------
__device__ __forceinline__ uint32_t smem_u32(const void* p) {
    uint32_t a;
    asm("{ .reg .u64 t; cvta.to.shared.u64 t, %1; cvt.u32.u64 %0, t; }" : "=r"(a) : "l"(p));
    return a;
}
__device__ __forceinline__ void cpa16(uint32_t dst, const void* src) {
    asm volatile("cp.async.cg.shared.global [%0], [%1], 16;" :: "r"(dst), "l"(src));
}
__device__ __forceinline__ void cpa_commit() {
    asm volatile("cp.async.commit_group;" ::: "memory");
}
template <int N> __device__ __forceinline__ void cpa_wait() {
    asm volatile("cp.async.wait_group %0;" :: "n"(N) : "memory");
}
__device__ __forceinline__ void ldm4(uint32_t* r, uint32_t addr) {
    asm volatile("ldmatrix.sync.aligned.m8n8.x4.shared.b16 {%0,%1,%2,%3}, [%4];"
                 : "=r"(r[0]), "=r"(r[1]), "=r"(r[2]), "=r"(r[3]) : "r"(addr));
}
__device__ __forceinline__ void mma16816h(float* c, const uint32_t* a,
                                          uint32_t b0, uint32_t b1) {
    asm volatile(
        "mma.sync.aligned.m16n8k16.row.col.f32.f16.f16.f32 "
        "{%0,%1,%2,%3}, {%4,%5,%6,%7}, {%8,%9}, {%0,%1,%2,%3};"
        : "+f"(c[0]), "+f"(c[1]), "+f"(c[2]), "+f"(c[3])
        : "r"(a[0]), "r"(a[1]), "r"(a[2]), "r"(a[3]), "r"(b0), "r"(b1));
}

// ---------------- conversion / init kernels -------------------------------------
__global__ void k_cvt_x(const float* __restrict__ x) {
    long long i4 = (long long)blockIdx.x * blockDim.x + threadIdx.x;
    if (i4 >= (long long)Mpad * 128) return;
    long long row = i4 >> 7;
    float4 v = make_float4(0.f, 0.f, 0.f, 0.f);
    if (row < Nn) v = ((const float4*)x)[i4];
    __half2 p0, p1;
    p0.x = __float2half_rn(v.x); p0.y = __float2half_rn(v.y);
    p1.x = __float2half_rn(v.z); p1.y = __float2half_rn(v.w);
    *(__half2*)(g_xh + i4 * 4)     = p0;
    *(__half2*)(g_xh + i4 * 4 + 2) = p1;
}

__global__ void k_init_misc(const float* __restrict__ W,
                            const float* __restrict__ W_out) {
    int idx = blockIdx.x * blockDim.x + threadIdx.x;
    if (idx < 512 * 512) {
        int n = idx >> 9, k = idx & 511;
        float v = W[(size_t)(n >> 6) * (512 * 64) + (size_t)k * 64 + (n & 63)];
        g_bh[idx] = __float2half_rn(v);
    }
    if (idx < 64 * 512) {
        int n = idx >> 9, k = idx & 511;
        g_b2[idx] = __float2half_rn(W_out[(size_t)k * 64 + n]);
    }
    if (idx < Nn) g_cnt[idx] = 0;
}

// ---------------- fp16 HMMA GEMM1 (+f1 epilogue), 2 CTAs/SM, 1 sync/iter --------
#define A_OFF 0
#define B_OFF 10240
#define STAGE 20480
#define SMEM_GEMM_TOTAL (2 * STAGE)

__device__ __forceinline__ void load_stage(uint32_t s, int t, int m0, int n0, int kc) {
    int k0 = kc * 32;
#pragma unroll
    for (int i = 0; i < 2; i++) {
        int idx = t + i * 256;
        int r = idx >> 2;
        int c = idx & 3;
        uint32_t d = s + (uint32_t)(r * 80 + c * 16);
        size_t sa = (size_t)(m0 + r) * 512 + k0 + c * 8;
        size_t sbg = (size_t)(n0 + r) * 512 + k0 + c * 8;
        cpa16(d + A_OFF, g_xh + sa);
        cpa16(d + B_OFF, g_bh + sbg);
    }
    cpa_commit();
}

__global__ void __launch_bounds__(256, 2) k_gemm1_mma(const float* __restrict__ a_vec) {
    extern __shared__ char smem[];
    __shared__ float s_ad[2][64], s_as[2][64];
    uint32_t sb = smem_u32(smem);
    const int t = threadIdx.x;
    const int lane = t & 31, w = t >> 5;
    const int wm = w & 3, wn = w >> 2;
    const int m0 = blockIdx.x * 128, n0 = blockIdx.y * 128;

    if (t < 128) {
        int hh = t >> 6, j = t & 63;
        int gh = blockIdx.y * 2 + hh;
        s_ad[hh][j] = a_vec[gh * 128 + j];
        s_as[hh][j] = a_vec[gh * 128 + 64 + j];
    }

    float acc[2][8][4];
#pragma unroll
    for (int mf = 0; mf < 2; mf++)
#pragma unroll
        for (int nf = 0; nf < 8; nf++)
#pragma unroll
            for (int q = 0; q < 4; q++) acc[mf][nf][q] = 0.f;

    load_stage(sb, t, m0, n0, 0);

    const int a_row = wm * 32 + (lane & 15);
    const int a_colb = (lane >> 4) * 8;
    const int b_row = wn * 64 + ((lane >> 4) & 1) * 8 + (lane & 7);
    const int b_colb = ((lane >> 3) & 1) * 8;

    for (int kc = 0; kc < 16; kc++) {
        uint32_t s = sb + (uint32_t)(kc & 1) * STAGE;
        cpa_wait<0>();
        __syncthreads();   // stage kc ready; all warps done reading buf (kc+1)&1
        if (kc + 1 < 16) load_stage(sb + (uint32_t)((kc + 1) & 1) * STAGE, t, m0, n0, kc + 1);

#pragma unroll
        for (int ks = 0; ks < 2; ks++) {
            uint32_t ah[2][4];
#pragma unroll
            for (int mf = 0; mf < 2; mf++) {
                uint32_t ad = s + A_OFF +
                    (uint32_t)((a_row + mf * 16) * 80 + (ks * 16 + a_colb) * 2);
                ldm4(ah[mf], ad);
            }
#pragma unroll
            for (int nb = 0; nb < 4; nb++) {
                uint32_t bh4[4];
                uint32_t bd = s + B_OFF +
                    (uint32_t)((b_row + nb * 16) * 80 + (ks * 16 + b_colb) * 2);
                ldm4(bh4, bd);
#pragma unroll
                for (int mf = 0; mf < 2; mf++)
#pragma unroll
                    for (int half = 0; half < 2; half++) {
                        float* c = acc[mf][nb * 2 + half];
                        mma16816h(c, ah[mf], bh4[half * 2], bh4[half * 2 + 1]);
                    }
            }
        }
    }

    const int ghead = blockIdx.y * 2 + wn;
#pragma unroll
    for (int mf = 0; mf < 2; mf++) {
        int rbase = m0 + wm * 32 + mf * 16 + (lane >> 2);
#pragma unroll
        for (int nf = 0; nf < 8; nf++) {
            int cc = n0 + wn * 64 + nf * 8 + (lane & 3) * 2;
            float* c = acc[mf][nf];
            if (rbase < Nn) {
                __half2 p;
                p.x = __float2half_rn(c[0]);
                p.y = __float2half_rn(c[1]);
                *(__half2*)(g_Whb + (size_t)rbase * 512 + cc) = p;
            }
            if (rbase + 8 < Nn) {
                __half2 p;
                p.x = __float2half_rn(c[2]);
                p.y = __float2half_rn(c[3]);
                *(__half2*)(g_Whb + (size_t)(rbase + 8) * 512 + cc) = p;
            }
        }
#pragma unroll
        for (int half = 0; half < 2; half++) {
            float pd = 0.f, ps = 0.f;
#pragma unroll
            for (int nf = 0; nf < 8; nf++) {
                int j0 = nf * 8 + (lane & 3) * 2;
                float c0 = acc[mf][nf][half * 2 + 0];
                float c1 = acc[mf][nf][half * 2 + 1];
                pd += c0 * s_ad[wn][j0] + c1 * s_ad[wn][j0 + 1];
                ps += c0 * s_as[wn][j0] + c1 * s_as[wn][j0 + 1];
            }
            pd += __shfl_xor_sync(0xffffffffu, pd, 1);
            pd += __shfl_xor_sync(0xffffffffu, pd, 2);
            ps += __shfl_xor_sync(0xffffffffu, ps, 1);
            ps += __shfl_xor_sync(0xffffffffu, ps, 2);
            int r = rbase + half * 8;
            if ((lane & 3) == 0 && r < Nn) {
                g_fd1[r * 8 + ghead] = pd;
                g_fs1[r * 8 + ghead] = ps;
            }
        }
    }
}

// ---------------- fp16 HMMA GEMM2 (+f2 epilogue), 2 CTAs/SM, 1 sync/iter --------
#define A2_OFF 0
#define B2_OFF 10240
#define STAGE2 15360
#define SMEM_GEMM2_TOTAL (2 * STAGE2)

__device__ __forceinline__ void load_stage2(uint32_t s, int t, int m0, int kc) {
    int k0 = kc * 32;
#pragma unroll
    for (int i = 0; i < 2; i++) {
        int idx = t + i * 256;
        int r = idx >> 2;
        int c = idx & 3;
        uint32_t d = s + (uint32_t)(r * 80 + c * 16);
        size_t sa = (size_t)(m0 + r) * 512 + k0 + c * 8;
        cpa16(d + A2_OFF, g_h1 + sa);
    }
    if (t < 256) {
        int r = t >> 2, c = t & 3;
        uint32_t d = s + (uint32_t)(r * 80 + c * 16);
        size_t sbg = (size_t)r * 512 + k0 + c * 8;
        cpa16(d + B2_OFF, g_b2 + sbg);
    }
    cpa_commit();
}

__global__ void __launch_bounds__(256, 2) k_gemm2_mma(const float* __restrict__ a_out) {
    extern __shared__ char smem[];
    __shared__ float s_a2d[64], s_a2s[64];
    __shared__ float s_pd[2][128], s_ps[2][128];
    uint32_t sb = smem_u32(smem);
    const int t = threadIdx.x;
    const int lane = t & 31, w = t >> 5;
    const int wm = w & 3, wn = w >> 2;
    const int m0 = blockIdx.x * 128;

    if (t < 64) {
        s_a2d[t] = a_out[t];
        s_a2s[t] = a_out[64 + t];
    }

    float acc[2][4][4];
#pragma unroll
    for (int mf = 0; mf < 2; mf++)
#pragma unroll
        for (int nf = 0; nf < 4; nf++)
#pragma unroll
            for (int q = 0; q < 4; q++) acc[mf][nf][q] = 0.f;

    load_stage2(sb, t, m0, 0);

    const int a_row = wm * 32 + (lane & 15);
    const int a_colb = (lane >> 4) * 8;
    const int b_row = wn * 32 + ((lane >> 4) & 1) * 8 + (lane & 7);
    const int b_colb = ((lane >> 3) & 1) * 8;

    for (int kc = 0; kc < 16; kc++) {
        uint32_t s = sb + (uint32_t)(kc & 1) * STAGE2;
        cpa_wait<0>();
        __syncthreads();
        if (kc + 1 < 16) load_stage2(sb + (uint32_t)((kc + 1) & 1) * STAGE2, t, m0, kc + 1);

#pragma unroll
        for (int ks = 0; ks < 2; ks++) {
            uint32_t ah[2][4];
#pragma unroll
            for (int mf = 0; mf < 2; mf++) {
                uint32_t ad = s + A2_OFF +
                    (uint32_t)((a_row + mf * 16) * 80 + (ks * 16 + a_colb) * 2);
                ldm4(ah[mf], ad);
            }
#pragma unroll
            for (int nb = 0; nb < 2; nb++) {
                uint32_t bh4[4];
                uint32_t bd = s + B2_OFF +
                    (uint32_t)((b_row + nb * 16) * 80 + (ks * 16 + b_colb) * 2);
                ldm4(bh4, bd);
#pragma unroll
                for (int mf = 0; mf < 2; mf++)
#pragma unroll
                    for (int half = 0; half < 2; half++) {
                        float* c = acc[mf][nb * 2 + half];
                        mma16816h(c, ah[mf], bh4[half * 2], bh4[half * 2 + 1]);
                    }
            }
        }
    }

#pragma unroll
    for (int mf = 0; mf < 2; mf++) {
        int rbase = m0 + wm * 32 + mf * 16 + (lane >> 2);
#pragma unroll
        for (int nf = 0; nf < 4; nf++) {
            int cc = wn * 32 + nf * 8 + (lane & 3) * 2;
            float* c = acc[mf][nf];
            if (rbase < Nn) {
                __half2 p;
                p.x = __float2half_rn(c[0]);
                p.y = __float2half_rn(c[1]);
                *(__half2*)(g_Wh2h + (size_t)rbase * 64 + cc) = p;
            }
            if (rbase + 8 < Nn) {
                __half2 p;
                p.x = __float2half_rn(c[2]);
                p.y = __float2half_rn(c[3]);
                *(__half2*)(g_Wh2h + (size_t)(rbase + 8) * 64 + cc) = p;
            }
        }
#pragma unroll
        for (int half = 0; half < 2; half++) {
            float pd = 0.f, ps = 0.f;
#pragma unroll
            for (int nf = 0; nf < 4; nf++) {
                int j0 = wn * 32 + nf * 8 + (lane & 3) * 2;
                float c0 = acc[mf][nf][half * 2 + 0];
                float c1 = acc[mf][nf][half * 2 + 1];
                pd += c0 * s_a2d[j0] + c1 * s_a2d[j0 + 1];
                ps += c0 * s_a2s[j0] + c1 * s_a2s[j0 + 1];
            }
            pd += __shfl_xor_sync(0xffffffffu, pd, 1);
            pd += __shfl_xor_sync(0xffffffffu, pd, 2);
            ps += __shfl_xor_sync(0xffffffffu, ps, 1);
            ps += __shfl_xor_sync(0xffffffffu, ps, 2);
            int rl = wm * 32 + mf * 16 + (lane >> 2) + half * 8;
            if ((lane & 3) == 0) {
                s_pd[wn][rl] = pd;
                s_ps[wn][rl] = ps;
            }
        }
    }
    __syncthreads();
    if (t < 128) {
        int r = m0 + t;
        if (r < Nn) {
            g_fd2[r] = s_pd[0][t] + s_pd[1][t];
            g_fs2[r] = s_ps[0][t] + s_ps[1][t];
        }
    }
}

// ---------------- CSR build ------------------------------------------------
__global__ void k_hist(const int* __restrict__ row) {
    int e = blockIdx.x * blockDim.x + threadIdx.x;
    if (e < Ee) atomicAdd(&g_cnt[row[e]], 1);
}

__global__ void k_scan() {
    __shared__ int s_w[32];
    __shared__ int s_base, s_next;
    int t = threadIdx.x, lane = t & 31, wid = t >> 5;
    if (t == 0) s_base = 0;
    __syncthreads();
    for (int start = 0; start < Nn; start += 1024) {
        int i = start + t;
        int v = (i < Nn) ? g_cnt[i] : 0;
        int sc = v;
#pragma unroll
        for (int d = 1; d < 32; d <<= 1) {
            int u = __shfl_up_sync(0xffffffffu, sc, d);
            if (lane >= d) sc += u;
        }
        if (lane == 31) s_w[wid] = sc;
        __syncthreads();
        if (wid == 0) {
            int wsc = s_w[lane];
#pragma unroll
            for (int d = 1; d < 32; d <<= 1) {
                int u = __shfl_up_sync(0xffffffffu, wsc, d);
                if (lane >= d) wsc += u;
            }
            s_w[lane] = wsc;
            if (lane == 31) s_next = wsc;
        }
        __syncthreads();
        int base = s_base;
        int warpoff = (wid == 0) ? 0 : s_w[wid - 1];
        int ex = base + warpoff + sc - v;
        if (i < Nn) { g_off[i] = ex; g_cur[i] = ex; }
        __syncthreads();
        if (t == 0) s_base = base + s_next;
        __syncthreads();
    }
    if (t == 0) g_off[Nn] = s_base;
}

__global__ void k_scatter(const int* __restrict__ row, const int* __restrict__ col) {
    int e = blockIdx.x * blockDim.x + threadIdx.x;
    if (e < Ee) {
        int p = atomicAdd(&g_cur[row[e]], 1);
        g_cols[p] = col[e];
    }
}

// ---------------- layer1: fused logits + softmax + fp16 gather agg + ELU -----
__global__ void __launch_bounds__(256) k_agg1() {
    int i = blockIdx.x;
    int t = threadIdx.x;
    int o = g_off[i], oe = g_off[i + 1];
    __shared__ float s_red[32][8];
    __shared__ float s_mx[8], s_iv[8];
    __shared__ float s_att[32][8];
    __shared__ int   s_col[32];
    __shared__ float s_fd[8];
    int j = t >> 3, h = t & 7;

    if (t < 8) s_fd[t] = g_fd1[i * 8 + t];
    __syncthreads();
    float fdh = s_fd[h];

    // pass 1: max of lrelu(fd + fs[col])
    float mx = -3.4e38f;
    for (int p = o + j; p < oe; p += 32) {
        int c = g_cols[p];
        float v = fdh + g_fs1[c * 8 + h];
        v = v > 0.f ? v : ALPHA * v;
        mx = fmaxf(mx, v);
    }
    s_red[j][h] = mx;
    __syncthreads();
#pragma unroll
    for (int s = 16; s > 0; s >>= 1) {
        if (j < s) s_red[j][h] = fmaxf(s_red[j][h], s_red[j + s][h]);
        __syncthreads();
    }
    float mxh = s_red[0][h];
    __syncthreads();

    // pass 2: sum of exp
    float sm = 0.f;
    for (int p = o + j; p < oe; p += 32) {
        int c = g_cols[p];
        float v = fdh + g_fs1[c * 8 + h];
        v = v > 0.f ? v : ALPHA * v;
        sm += __expf(v - mxh);
    }
    s_red[j][h] = sm;
    __syncthreads();
#pragma unroll
    for (int s = 16; s > 0; s >>= 1) {
        if (j < s) s_red[j][h] += s_red[j + s][h];
        __syncthreads();
    }
    if (j == 0) {
        s_mx[h] = (oe > o) ? mxh : 0.f;
        s_iv[h] = (oe > o) ? 1.f / fmaxf(s_red[0][h], 1e-16f) : 0.f;
    }
    __syncthreads();

    // pass 3: chunked aggregation; dims (2t, 2t+1); head = t>>5
    int ha = t >> 5;
    float acc0 = 0.f, acc1 = 0.f;
    for (int base = o; base < oe; base += 32) {
        int cnt = min(32, oe - base);
        __syncthreads();
        if (j < cnt) {
            int c = g_cols[base + j];
            float v = fdh + g_fs1[c * 8 + h];
            v = v > 0.f ? v : ALPHA * v;
            s_att[j][h] = __expf(v - s_mx[h]) * s_iv[h];
        }
        if (t < cnt) s_col[t] = g_cols[base + t];
        __syncthreads();
        for (int q = 0; q < cnt; q++) {
            int c = s_col[q];
            const __half2* whc = (const __half2*)(g_Whb + (size_t)c * 512);
            float2 v = __half22float2(whc[t]);
            float wv = s_att[q][ha];
            acc0 = fmaf(wv, v.x, acc0);
            acc1 = fmaf(wv, v.y, acc1);
        }
    }
    float v0 = acc0 > 0.f ? acc0 : (__expf(acc0) - 1.f);
    float v1 = acc1 > 0.f ? acc1 : (__expf(acc1) - 1.f);
    __half2 p;
    p.x = __float2half_rn(v0);
    p.y = __float2half_rn(v1);
    *(__half2*)(g_h1 + (size_t)i * 512 + 2 * t) = p;
}

// ---------------- layer2: fused logits + softmax + aggregation ---------------
__global__ void __launch_bounds__(64) k_agg2(float* __restrict__ out) {
    int i = blockIdx.x;
    int t = threadIdx.x;  // 64
    int o = g_off[i], oe = g_off[i + 1];
    __shared__ float s_r[64];
    __shared__ float s_att[64];
    __shared__ int   s_col[64];
    float fd = g_fd2[i];

    float mx = -3.4e38f;
    for (int p = o + t; p < oe; p += 64) {
        float v = fd + g_fs2[g_cols[p]];
        v = v > 0.f ? v : ALPHA * v;
        mx = fmaxf(mx, v);
    }
    s_r[t] = mx;
    __syncthreads();
#pragma unroll
    for (int s = 32; s > 0; s >>= 1) {
        if (t < s) s_r[t] = fmaxf(s_r[t], s_r[t + s]);
        __syncthreads();
    }
    float M = s_r[0];
    __syncthreads();
    float sm = 0.f;
    for (int p = o + t; p < oe; p += 64) {
        float v = fd + g_fs2[g_cols[p]];
        v = v > 0.f ? v : ALPHA * v;
        sm += __expf(v - M);
    }
    s_r[t] = sm;
    __syncthreads();
#pragma unroll
    for (int s = 32; s > 0; s >>= 1) {
        if (t < s) s_r[t] += s_r[t + s];
        __syncthreads();
    }
    float iv = (oe > o) ? 1.f / fmaxf(s_r[0], 1e-16f) : 0.f;
    __syncthreads();

    float acc = 0.f;
    for (int base = o; base < oe; base += 64) {
        int cnt = min(64, oe - base);
        __syncthreads();
        if (t < cnt) {
            int c = g_cols[base + t];
            float v = fd + g_fs2[c];
            v = v > 0.f ? v : ALPHA * v;
            s_att[t] = __expf(v - M) * iv;
            s_col[t] = c;
        }
        __syncthreads();
        for (int q = 0; q < cnt; q++)
            acc = fmaf(s_att[q], __half2float(g_Wh2h[(size_t)s_col[q] * 64 + t]), acc);
    }
    out[(size_t)i * 64 + t] = acc;
}

// ---------------- launch -----------------------------------------------------
extern "C" void kernel_launch(void* const* d_in, const int* in_sizes, int n_in,
                              void* d_out, int out_size) {
    const float* x     = (const float*)d_in[0];
    const int*   row   = (const int*)  d_in[1];
    const int*   col   = (const int*)  d_in[2];
    const float* W     = (const float*)d_in[3];
    const float* a     = (const float*)d_in[4];
    const float* W_out = (const float*)d_in[5];
    const float* a_out = (const float*)d_in[6];
    float* out = (float*)d_out;

    const int EB = (Ee + 255) / 256;

    cudaFuncSetAttribute(k_gemm1_mma, cudaFuncAttributeMaxDynamicSharedMemorySize,
                         SMEM_GEMM_TOTAL);
    cudaFuncSetAttribute(k_gemm2_mma, cudaFuncAttributeMaxDynamicSharedMemorySize,
                         SMEM_GEMM2_TOTAL);

    k_cvt_x<<<(int)(((long long)Mpad * 128 + 255) / 256), 256>>>(x);       // 0
    k_init_misc<<<(512 * 512 + 255) / 256, 256>>>(W, W_out);               // 1
    k_hist<<<EB, 256>>>(row);                                              // 2
    k_gemm1_mma<<<dim3(Mpad / 128, 4), 256, SMEM_GEMM_TOTAL>>>(a);         // 3 <- profiled
    k_scan<<<1, 1024>>>();                                                 // 4
    k_scatter<<<EB, 256>>>(row, col);                                      // 5
    k_agg1<<<Nn, 256>>>();                                                 // 6
    k_gemm2_mma<<<Mpad / 128, 256, SMEM_GEMM2_TOTAL>>>(a_out);             // 7
    k_agg2<<<Nn, 64>>>(out);                                               // 8
}

// round 17
// speedup vs baseline: 1.0866x; 1.0348x over previous
#include <cuda_runtime.h>
#include <cuda_bf16.h>
#include <cuda_fp16.h>
#include <stdint.h>
#include <math.h>

// Problem constants
#define Nn    50000
#define Mpad  50048
#define Ee    800000
#define FEAT  512
#define HEADS 8
#define HID   64
#define C1    512
#define NC    64
#define ALPHA 0.2f

// ---------------- scratch -----------------------------------------------------
__device__ float g_fd1[Nn * HEADS];
__device__ float g_fs1[Nn * HEADS];
__device__ float g_fd2[Nn];
__device__ float g_fs2[Nn];
__device__ int   g_cnt[Nn];
__device__ int   g_off[Nn + 1];
__device__ int   g_cur[Nn];
__device__ int   g_cols[Ee];

// fp16 operands / intermediates
__device__ __align__(256) __half g_xh [(size_t)Mpad * 512];   // x in fp16
__device__ __align__(256) __half g_bh [512 * 512];            // W1t in fp16
__device__ __align__(256) __half g_Whb[(size_t)Nn * 512];     // layer1 Wh in fp16
__device__ __align__(256) __half g_h1 [(size_t)Mpad * 512];   // h1 fp16 (pad rows stay 0)
__device__ __align__(256) __half g_b2 [64 * 512];             // W_out_t in fp16
__device__ __align__(256) __half g_Wh2h[(size_t)Nn * 64];     // layer2 Wh in fp16

// ---------------- PTX helpers --------------------------------------------------
__device__ __forceinline__ uint32_t smem_u32(const void* p) {
    uint32_t a;
    asm("{ .reg .u64 t; cvta.to.shared.u64 t, %1; cvt.u32.u64 %0, t; }" : "=r"(a) : "l"(p));
    return a;
}
__device__ __forceinline__ void cpa16(uint32_t dst, const void* src) {
    asm volatile("cp.async.cg.shared.global [%0], [%1], 16;" :: "r"(dst), "l"(src));
}
__device__ __forceinline__ void cpa_commit() {
    asm volatile("cp.async.commit_group;" ::: "memory");
}
template <int N> __device__ __forceinline__ void cpa_wait() {
    asm volatile("cp.async.wait_group %0;" :: "n"(N) : "memory");
}
__device__ __forceinline__ void ldm4(uint32_t* r, uint32_t addr) {
    asm volatile("ldmatrix.sync.aligned.m8n8.x4.shared.b16 {%0,%1,%2,%3}, [%4];"
                 : "=r"(r[0]), "=r"(r[1]), "=r"(r[2]), "=r"(r[3]) : "r"(addr));
}
__device__ __forceinline__ void mma16816h(float* c, const uint32_t* a,
                                          uint32_t b0, uint32_t b1) {
    asm volatile(
        "mma.sync.aligned.m16n8k16.row.col.f32.f16.f16.f32 "
        "{%0,%1,%2,%3}, {%4,%5,%6,%7}, {%8,%9}, {%0,%1,%2,%3};"
        : "+f"(c[0]), "+f"(c[1]), "+f"(c[2]), "+f"(c[3])
        : "r"(a[0]), "r"(a[1]), "r"(a[2]), "r"(a[3]), "r"(b0), "r"(b1));
}

// ---------------- conversion / init kernels -------------------------------------
__global__ void k_cvt_x(const float* __restrict__ x) {
    long long i4 = (long long)blockIdx.x * blockDim.x + threadIdx.x;
    if (i4 >= (long long)Mpad * 128) return;
    long long row = i4 >> 7;
    float4 v = make_float4(0.f, 0.f, 0.f, 0.f);
    if (row < Nn) v = ((const float4*)x)[i4];
    __half2 p0, p1;
    p0.x = __float2half_rn(v.x); p0.y = __float2half_rn(v.y);
    p1.x = __float2half_rn(v.z); p1.y = __float2half_rn(v.w);
    *(__half2*)(g_xh + i4 * 4)     = p0;
    *(__half2*)(g_xh + i4 * 4 + 2) = p1;
}

__global__ void k_init_misc(const float* __restrict__ W,
                            const float* __restrict__ W_out) {
    int idx = blockIdx.x * blockDim.x + threadIdx.x;
    if (idx < 512 * 512) {
        int n = idx >> 9, k = idx & 511;
        float v = W[(size_t)(n >> 6) * (512 * 64) + (size_t)k * 64 + (n & 63)];
        g_bh[idx] = __float2half_rn(v);
    }
    if (idx < 64 * 512) {
        int n = idx >> 9, k = idx & 511;
        g_b2[idx] = __float2half_rn(W_out[(size_t)k * 64 + n]);
    }
    if (idx < Nn) g_cnt[idx] = 0;
}

// ---------------- fp16 HMMA GEMM1 (+f1 epilogue), 2 CTAs/SM, 1 sync/iter --------
#define A_OFF 0
#define B_OFF 10240
#define STAGE 20480
#define SMEM_GEMM_TOTAL (2 * STAGE)

__device__ __forceinline__ void load_stage(uint32_t s, int t, int m0, int n0, int kc) {
    int k0 = kc * 32;
#pragma unroll
    for (int i = 0; i < 2; i++) {
        int idx = t + i * 256;
        int r = idx >> 2;
        int c = idx & 3;
        uint32_t d = s + (uint32_t)(r * 80 + c * 16);
        size_t sa = (size_t)(m0 + r) * 512 + k0 + c * 8;
        size_t sbg = (size_t)(n0 + r) * 512 + k0 + c * 8;
        cpa16(d + A_OFF, g_xh + sa);
        cpa16(d + B_OFF, g_bh + sbg);
    }
    cpa_commit();
}

__global__ void __launch_bounds__(256, 2) k_gemm1_mma(const float* __restrict__ a_vec) {
    extern __shared__ char smem[];
    __shared__ float s_ad[2][64], s_as[2][64];
    uint32_t sb = smem_u32(smem);
    const int t = threadIdx.x;
    const int lane = t & 31, w = t >> 5;
    const int wm = w & 3, wn = w >> 2;
    const int m0 = blockIdx.x * 128, n0 = blockIdx.y * 128;

    if (t < 128) {
        int hh = t >> 6, j = t & 63;
        int gh = blockIdx.y * 2 + hh;
        s_ad[hh][j] = a_vec[gh * 128 + j];
        s_as[hh][j] = a_vec[gh * 128 + 64 + j];
    }

    float acc[2][8][4];
#pragma unroll
    for (int mf = 0; mf < 2; mf++)
#pragma unroll
        for (int nf = 0; nf < 8; nf++)
#pragma unroll
            for (int q = 0; q < 4; q++) acc[mf][nf][q] = 0.f;

    load_stage(sb, t, m0, n0, 0);

    const int a_row = wm * 32 + (lane & 15);
    const int a_colb = (lane >> 4) * 8;
    const int b_row = wn * 64 + ((lane >> 4) & 1) * 8 + (lane & 7);
    const int b_colb = ((lane >> 3) & 1) * 8;

    for (int kc = 0; kc < 16; kc++) {
        uint32_t s = sb + (uint32_t)(kc & 1) * STAGE;
        cpa_wait<0>();
        __syncthreads();   // stage kc ready; all warps done reading buf (kc+1)&1
        if (kc + 1 < 16) load_stage(sb + (uint32_t)((kc + 1) & 1) * STAGE, t, m0, n0, kc + 1);

#pragma unroll
        for (int ks = 0; ks < 2; ks++) {
            uint32_t ah[2][4];
#pragma unroll
            for (int mf = 0; mf < 2; mf++) {
                uint32_t ad = s + A_OFF +
                    (uint32_t)((a_row + mf * 16) * 80 + (ks * 16 + a_colb) * 2);
                ldm4(ah[mf], ad);
            }
#pragma unroll
            for (int nb = 0; nb < 4; nb++) {
                uint32_t bh4[4];
                uint32_t bd = s + B_OFF +
                    (uint32_t)((b_row + nb * 16) * 80 + (ks * 16 + b_colb) * 2);
                ldm4(bh4, bd);
#pragma unroll
                for (int mf = 0; mf < 2; mf++)
#pragma unroll
                    for (int half = 0; half < 2; half++) {
                        float* c = acc[mf][nb * 2 + half];
                        mma16816h(c, ah[mf], bh4[half * 2], bh4[half * 2 + 1]);
                    }
            }
        }
    }

    const int ghead = blockIdx.y * 2 + wn;
#pragma unroll
    for (int mf = 0; mf < 2; mf++) {
        int rbase = m0 + wm * 32 + mf * 16 + (lane >> 2);
#pragma unroll
        for (int nf = 0; nf < 8; nf++) {
            int cc = n0 + wn * 64 + nf * 8 + (lane & 3) * 2;
            float* c = acc[mf][nf];
            if (rbase < Nn) {
                __half2 p;
                p.x = __float2half_rn(c[0]);
                p.y = __float2half_rn(c[1]);
                *(__half2*)(g_Whb + (size_t)rbase * 512 + cc) = p;
            }
            if (rbase + 8 < Nn) {
                __half2 p;
                p.x = __float2half_rn(c[2]);
                p.y = __float2half_rn(c[3]);
                *(__half2*)(g_Whb + (size_t)(rbase + 8) * 512 + cc) = p;
            }
        }
#pragma unroll
        for (int half = 0; half < 2; half++) {
            float pd = 0.f, ps = 0.f;
#pragma unroll
            for (int nf = 0; nf < 8; nf++) {
                int j0 = nf * 8 + (lane & 3) * 2;
                float c0 = acc[mf][nf][half * 2 + 0];
                float c1 = acc[mf][nf][half * 2 + 1];
                pd += c0 * s_ad[wn][j0] + c1 * s_ad[wn][j0 + 1];
                ps += c0 * s_as[wn][j0] + c1 * s_as[wn][j0 + 1];
            }
            pd += __shfl_xor_sync(0xffffffffu, pd, 1);
            pd += __shfl_xor_sync(0xffffffffu, pd, 2);
            ps += __shfl_xor_sync(0xffffffffu, ps, 1);
            ps += __shfl_xor_sync(0xffffffffu, ps, 2);
            int r = rbase + half * 8;
            if ((lane & 3) == 0 && r < Nn) {
                g_fd1[r * 8 + ghead] = pd;
                g_fs1[r * 8 + ghead] = ps;
            }
        }
    }
}

// ---------------- fp16 HMMA GEMM2 (+f2 epilogue), 2 CTAs/SM (R14 loop) ----------
#define A2_OFF 0
#define B2_OFF 10240
#define STAGE2 15360
#define SMEM_GEMM2_TOTAL (2 * STAGE2)

__device__ __forceinline__ void load_stage2(uint32_t s, int t, int m0, int kc) {
    int k0 = kc * 32;
#pragma unroll
    for (int i = 0; i < 2; i++) {
        int idx = t + i * 256;
        int r = idx >> 2;
        int c = idx & 3;
        uint32_t d = s + (uint32_t)(r * 80 + c * 16);
        size_t sa = (size_t)(m0 + r) * 512 + k0 + c * 8;
        cpa16(d + A2_OFF, g_h1 + sa);
    }
    if (t < 256) {
        int r = t >> 2, c = t & 3;
        uint32_t d = s + (uint32_t)(r * 80 + c * 16);
        size_t sbg = (size_t)r * 512 + k0 + c * 8;
        cpa16(d + B2_OFF, g_b2 + sbg);
    }
    cpa_commit();
}

__global__ void __launch_bounds__(256, 2) k_gemm2_mma(const float* __restrict__ a_out) {
    extern __shared__ char smem[];
    __shared__ float s_a2d[64], s_a2s[64];
    __shared__ float s_pd[2][128], s_ps[2][128];
    uint32_t sb = smem_u32(smem);
    const int t = threadIdx.x;
    const int lane = t & 31, w = t >> 5;
    const int wm = w & 3, wn = w >> 2;
    const int m0 = blockIdx.x * 128;

    if (t < 64) {
        s_a2d[t] = a_out[t];
        s_a2s[t] = a_out[64 + t];
    }

    float acc[2][4][4];
#pragma unroll
    for (int mf = 0; mf < 2; mf++)
#pragma unroll
        for (int nf = 0; nf < 4; nf++)
#pragma unroll
            for (int q = 0; q < 4; q++) acc[mf][nf][q] = 0.f;

    load_stage2(sb, t, m0, 0);

    const int a_row = wm * 32 + (lane & 15);
    const int a_colb = (lane >> 4) * 8;
    const int b_row = wn * 32 + ((lane >> 4) & 1) * 8 + (lane & 7);
    const int b_colb = ((lane >> 3) & 1) * 8;

    for (int kc = 0; kc < 16; kc++) {
        uint32_t s = sb + (uint32_t)(kc & 1) * STAGE2;
        if (kc + 1 < 16) load_stage2(sb + (uint32_t)((kc + 1) & 1) * STAGE2, t, m0, kc + 1);
        if (kc + 1 < 16) { cpa_wait<1>(); } else { cpa_wait<0>(); }
        __syncthreads();

#pragma unroll
        for (int ks = 0; ks < 2; ks++) {
            uint32_t ah[2][4];
#pragma unroll
            for (int mf = 0; mf < 2; mf++) {
                uint32_t ad = s + A2_OFF +
                    (uint32_t)((a_row + mf * 16) * 80 + (ks * 16 + a_colb) * 2);
                ldm4(ah[mf], ad);
            }
#pragma unroll
            for (int nb = 0; nb < 2; nb++) {
                uint32_t bh4[4];
                uint32_t bd = s + B2_OFF +
                    (uint32_t)((b_row + nb * 16) * 80 + (ks * 16 + b_colb) * 2);
                ldm4(bh4, bd);
#pragma unroll
                for (int mf = 0; mf < 2; mf++)
#pragma unroll
                    for (int half = 0; half < 2; half++) {
                        float* c = acc[mf][nb * 2 + half];
                        mma16816h(c, ah[mf], bh4[half * 2], bh4[half * 2 + 1]);
                    }
            }
        }
        __syncthreads();
    }

#pragma unroll
    for (int mf = 0; mf < 2; mf++) {
        int rbase = m0 + wm * 32 + mf * 16 + (lane >> 2);
#pragma unroll
        for (int nf = 0; nf < 4; nf++) {
            int cc = wn * 32 + nf * 8 + (lane & 3) * 2;
            float* c = acc[mf][nf];
            if (rbase < Nn) {
                __half2 p;
                p.x = __float2half_rn(c[0]);
                p.y = __float2half_rn(c[1]);
                *(__half2*)(g_Wh2h + (size_t)rbase * 64 + cc) = p;
            }
            if (rbase + 8 < Nn) {
                __half2 p;
                p.x = __float2half_rn(c[2]);
                p.y = __float2half_rn(c[3]);
                *(__half2*)(g_Wh2h + (size_t)(rbase + 8) * 64 + cc) = p;
            }
        }
#pragma unroll
        for (int half = 0; half < 2; half++) {
            float pd = 0.f, ps = 0.f;
#pragma unroll
            for (int nf = 0; nf < 4; nf++) {
                int j0 = wn * 32 + nf * 8 + (lane & 3) * 2;
                float c0 = acc[mf][nf][half * 2 + 0];
                float c1 = acc[mf][nf][half * 2 + 1];
                pd += c0 * s_a2d[j0] + c1 * s_a2d[j0 + 1];
                ps += c0 * s_a2s[j0] + c1 * s_a2s[j0 + 1];
            }
            pd += __shfl_xor_sync(0xffffffffu, pd, 1);
            pd += __shfl_xor_sync(0xffffffffu, pd, 2);
            ps += __shfl_xor_sync(0xffffffffu, ps, 1);
            ps += __shfl_xor_sync(0xffffffffu, ps, 2);
            int rl = wm * 32 + mf * 16 + (lane >> 2) + half * 8;
            if ((lane & 3) == 0) {
                s_pd[wn][rl] = pd;
                s_ps[wn][rl] = ps;
            }
        }
    }
    __syncthreads();
    if (t < 128) {
        int r = m0 + t;
        if (r < Nn) {
            g_fd2[r] = s_pd[0][t] + s_pd[1][t];
            g_fs2[r] = s_ps[0][t] + s_ps[1][t];
        }
    }
}

// ---------------- CSR build ------------------------------------------------
__global__ void k_hist(const int* __restrict__ row) {
    int e = blockIdx.x * blockDim.x + threadIdx.x;
    if (e < Ee) atomicAdd(&g_cnt[row[e]], 1);
}

__global__ void k_scan() {
    __shared__ int s_w[32];
    __shared__ int s_base, s_next;
    int t = threadIdx.x, lane = t & 31, wid = t >> 5;
    if (t == 0) s_base = 0;
    __syncthreads();
    for (int start = 0; start < Nn; start += 1024) {
        int i = start + t;
        int v = (i < Nn) ? g_cnt[i] : 0;
        int sc = v;
#pragma unroll
        for (int d = 1; d < 32; d <<= 1) {
            int u = __shfl_up_sync(0xffffffffu, sc, d);
            if (lane >= d) sc += u;
        }
        if (lane == 31) s_w[wid] = sc;
        __syncthreads();
        if (wid == 0) {
            int wsc = s_w[lane];
#pragma unroll
            for (int d = 1; d < 32; d <<= 1) {
                int u = __shfl_up_sync(0xffffffffu, wsc, d);
                if (lane >= d) wsc += u;
            }
            s_w[lane] = wsc;
            if (lane == 31) s_next = wsc;
        }
        __syncthreads();
        int base = s_base;
        int warpoff = (wid == 0) ? 0 : s_w[wid - 1];
        int ex = base + warpoff + sc - v;
        if (i < Nn) { g_off[i] = ex; g_cur[i] = ex; }
        __syncthreads();
        if (t == 0) s_base = base + s_next;
        __syncthreads();
    }
    if (t == 0) g_off[Nn] = s_base;
}

__global__ void k_scatter(const int* __restrict__ row, const int* __restrict__ col) {
    int e = blockIdx.x * blockDim.x + threadIdx.x;
    if (e < Ee) {
        int p = atomicAdd(&g_cur[row[e]], 1);
        g_cols[p] = col[e];
    }
}

// ---------------- layer1: fused logits + softmax + fp16 gather agg + ELU -----
__global__ void __launch_bounds__(256) k_agg1() {
    int i = blockIdx.x;
    int t = threadIdx.x;
    int o = g_off[i], oe = g_off[i + 1];
    __shared__ float s_red[32][8];
    __shared__ float s_mx[8], s_iv[8];
    __shared__ float s_att[32][8];
    __shared__ int   s_col[32];
    __shared__ float s_fd[8];
    int j = t >> 3, h = t & 7;

    if (t < 8) s_fd[t] = g_fd1[i * 8 + t];
    __syncthreads();
    float fdh = s_fd[h];

    // pass 1: max of lrelu(fd + fs[col])
    float mx = -3.4e38f;
    for (int p = o + j; p < oe; p += 32) {
        int c = g_cols[p];
        float v = fdh + g_fs1[c * 8 + h];
        v = v > 0.f ? v : ALPHA * v;
        mx = fmaxf(mx, v);
    }
    s_red[j][h] = mx;
    __syncthreads();
#pragma unroll
    for (int s = 16; s > 0; s >>= 1) {
        if (j < s) s_red[j][h] = fmaxf(s_red[j][h], s_red[j + s][h]);
        __syncthreads();
    }
    float mxh = s_red[0][h];
    __syncthreads();

    // pass 2: sum of exp
    float sm = 0.f;
    for (int p = o + j; p < oe; p += 32) {
        int c = g_cols[p];
        float v = fdh + g_fs1[c * 8 + h];
        v = v > 0.f ? v : ALPHA * v;
        sm += __expf(v - mxh);
    }
    s_red[j][h] = sm;
    __syncthreads();
#pragma unroll
    for (int s = 16; s > 0; s >>= 1) {
        if (j < s) s_red[j][h] += s_red[j + s][h];
        __syncthreads();
    }
    if (j == 0) {
        s_mx[h] = (oe > o) ? mxh : 0.f;
        s_iv[h] = (oe > o) ? 1.f / fmaxf(s_red[0][h], 1e-16f) : 0.f;
    }
    __syncthreads();

    // pass 3: chunked aggregation; dims (2t, 2t+1); head = t>>5
    int ha = t >> 5;
    float acc0 = 0.f, acc1 = 0.f;
    for (int base = o; base < oe; base += 32) {
        int cnt = min(32, oe - base);
        __syncthreads();
        if (j < cnt) {
            int c = g_cols[base + j];
            float v = fdh + g_fs1[c * 8 + h];
            v = v > 0.f ? v : ALPHA * v;
            s_att[j][h] = __expf(v - s_mx[h]) * s_iv[h];
        }
        if (t < cnt) s_col[t] = g_cols[base + t];
        __syncthreads();
        for (int q = 0; q < cnt; q++) {
            int c = s_col[q];
            const __half2* whc = (const __half2*)(g_Whb + (size_t)c * 512);
            float2 v = __half22float2(whc[t]);
            float wv = s_att[q][ha];
            acc0 = fmaf(wv, v.x, acc0);
            acc1 = fmaf(wv, v.y, acc1);
        }
    }
    float v0 = acc0 > 0.f ? acc0 : (__expf(acc0) - 1.f);
    float v1 = acc1 > 0.f ? acc1 : (__expf(acc1) - 1.f);
    __half2 p;
    p.x = __float2half_rn(v0);
    p.y = __float2half_rn(v1);
    *(__half2*)(g_h1 + (size_t)i * 512 + 2 * t) = p;
}

// ---------------- layer2: fused logits + softmax + aggregation ---------------
__global__ void __launch_bounds__(64) k_agg2(float* __restrict__ out) {
    int i = blockIdx.x;
    int t = threadIdx.x;  // 64
    int o = g_off[i], oe = g_off[i + 1];
    __shared__ float s_r[64];
    __shared__ float s_att[64];
    __shared__ int   s_col[64];
    float fd = g_fd2[i];

    float mx = -3.4e38f;
    for (int p = o + t; p < oe; p += 64) {
        float v = fd + g_fs2[g_cols[p]];
        v = v > 0.f ? v : ALPHA * v;
        mx = fmaxf(mx, v);
    }
    s_r[t] = mx;
    __syncthreads();
#pragma unroll
    for (int s = 32; s > 0; s >>= 1) {
        if (t < s) s_r[t] = fmaxf(s_r[t], s_r[t + s]);
        __syncthreads();
    }
    float M = s_r[0];
    __syncthreads();
    float sm = 0.f;
    for (int p = o + t; p < oe; p += 64) {
        float v = fd + g_fs2[g_cols[p]];
        v = v > 0.f ? v : ALPHA * v;
        sm += __expf(v - M);
    }
    s_r[t] = sm;
    __syncthreads();
#pragma unroll
    for (int s = 32; s > 0; s >>= 1) {
        if (t < s) s_r[t] += s_r[t + s];
        __syncthreads();
    }
    float iv = (oe > o) ? 1.f / fmaxf(s_r[0], 1e-16f) : 0.f;
    __syncthreads();

    float acc = 0.f;
    for (int base = o; base < oe; base += 64) {
        int cnt = min(64, oe - base);
        __syncthreads();
        if (t < cnt) {
            int c = g_cols[base + t];
            float v = fd + g_fs2[c];
            v = v > 0.f ? v : ALPHA * v;
            s_att[t] = __expf(v - M) * iv;
            s_col[t] = c;
        }
        __syncthreads();
        for (int q = 0; q < cnt; q++)
            acc = fmaf(s_att[q], __half2float(g_Wh2h[(size_t)s_col[q] * 64 + t]), acc);
    }
    out[(size_t)i * 64 + t] = acc;
}

// ---------------- launch -----------------------------------------------------
extern "C" void kernel_launch(void* const* d_in, const int* in_sizes, int n_in,
                              void* d_out, int out_size) {
    const float* x     = (const float*)d_in[0];
    const int*   row   = (const int*)  d_in[1];
    const int*   col   = (const int*)  d_in[2];
    const float* W     = (const float*)d_in[3];
    const float* a     = (const float*)d_in[4];
    const float* W_out = (const float*)d_in[5];
    const float* a_out = (const float*)d_in[6];
    float* out = (float*)d_out;

    const int EB = (Ee + 255) / 256;

    cudaFuncSetAttribute(k_gemm1_mma, cudaFuncAttributeMaxDynamicSharedMemorySize,
                         SMEM_GEMM_TOTAL);
    cudaFuncSetAttribute(k_gemm2_mma, cudaFuncAttributeMaxDynamicSharedMemorySize,
                         SMEM_GEMM2_TOTAL);

    k_cvt_x<<<(int)(((long long)Mpad * 128 + 255) / 256), 256>>>(x);       // 0
    k_init_misc<<<(512 * 512 + 255) / 256, 256>>>(W, W_out);               // 1
    k_hist<<<EB, 256>>>(row);                                              // 2
    k_gemm1_mma<<<dim3(Mpad / 128, 4), 256, SMEM_GEMM_TOTAL>>>(a);         // 3 <- profiled
    k_scan<<<1, 1024>>>();                                                 // 4
    k_scatter<<<EB, 256>>>(row, col);                                      // 5
    k_agg1<<<Nn, 256>>>();                                                 // 6
    k_gemm2_mma<<<Mpad / 128, 256, SMEM_GEMM2_TOTAL>>>(a_out);             // 7
    k_agg2<<<Nn, 64>>>(out);                                               // 8
}